// round 7
// baseline (speedup 1.0000x reference)
#include <cuda_runtime.h>
#include <cuda_bf16.h>
#include <cstdint>

// BarycentricPooling — trajectory-faithful stabilized-linear Sinkhorn, low-sync.
//
// N=20000, S=16, D=128, K=64, B=256, eps=0.1, 21 sweeps (1 log + 20 linear).
//
// Block = 64 threads = 2 warps, one node. Thread t owns column k=t (g-direction).
// f-direction warp-redundant: lane l covers row s=l&15, k-half l>>4 (32 k),
// merged by one shfl_xor(16); u is warp-private smem -> one __syncthreads per
// sweep (V exchange), double-buffered V.
//
// R6 failure root cause (rel_err 8.6e-2): without re-absorption, columns whose
// sums underflow f32 (legit cs down to ~2^-190) get clamped -> V=1e30 instead
// of 2^+190 -> the column's converged mass b_k=1/64 vanishes from every
// f-update. Fix: re-absorb (u,V) into W at it in {1,2,3,4,8,12,16} — each
// absorb multiplies dead columns by ~1e30, restoring them within ~2 absorbs
// (the ratchet that made R4 pass at 4.5e-4).

#define SS    16
#define KK    64
#define DD    128
#define BMAX  256
#define MST   68   // Msh row stride in floats (272B = 17*16, 16B aligned)
#define L2E_EPS 14.4269504088896340736f   // log2(e)/0.1

typedef unsigned long long ull;

__device__ float4 g_ctf4[(DD/4)*KK];   // codebook transposed: [d4][k] float4
__device__ float  g_y2[KK];
__device__ float  g_lb2[KK];
__device__ float  g_bk[KK];
__device__ float  g_sums[BMAX*KK];
__device__ float  g_counts[BMAX];

__device__ __forceinline__ float ex2a(float x){ float y; asm("ex2.approx.ftz.f32 %0, %1;" : "=f"(y) : "f"(x)); return y; }
__device__ __forceinline__ float lg2a(float x){ float y; asm("lg2.approx.ftz.f32 %0, %1;" : "=f"(y) : "f"(x)); return y; }
__device__ __forceinline__ float rcpa(float x){ float y; asm("rcp.approx.ftz.f32 %0, %1;" : "=f"(y) : "f"(x)); return y; }
__device__ __forceinline__ void ffma2(ull& d, ull a, ull b){
    asm("fma.rn.f32x2 %0, %1, %2, %0;" : "+l"(d) : "l"(a), "l"(b));
}
__device__ __forceinline__ ull fmul2(ull a, ull b){
    ull r; asm("mul.rn.f32x2 %0, %1, %2;" : "=l"(r) : "l"(a), "l"(b)); return r;
}
__device__ __forceinline__ float unpack_add(ull v){
    float lo = __uint_as_float((unsigned)(v & 0xffffffffull));
    float hi = __uint_as_float((unsigned)(v >> 32));
    return lo + hi;
}
__device__ __forceinline__ ull pk2(float lo, float hi){
    ull r; asm("mov.b64 %0, {%1,%2};" : "=l"(r) : "f"(lo), "f"(hi)); return r;
}

// ---------------------------------------------------------------------------
__global__ void prep_kernel(const float* __restrict__ cb,
                            const float* __restrict__ lp)
{
    __shared__ float sm[2], se[2];
    int tid = threadIdx.x;
    int i = blockIdx.x * blockDim.x + tid;

    if (i < BMAX*KK) g_sums[i] = 0.0f;
    if (i < BMAX)    g_counts[i] = 0.0f;
    if (i < (DD/4)*KK) {
        int d4 = i / KK, k = i % KK;
        const float* r = cb + k*DD + 4*d4;
        g_ctf4[i] = make_float4(r[0], r[1], r[2], r[3]);
    }
    if (blockIdx.x == 0) {
        if (tid < KK*4) {
            int k = tid >> 2, q = tid & 3;
            const float4* r = (const float4*)(cb + k*DD + q*32);
            float s = 0.0f;
            #pragma unroll
            for (int j = 0; j < 8; j++) { float4 v = r[j]; s += v.x*v.x + v.y*v.y + v.z*v.z + v.w*v.w; }
            s += __shfl_xor_sync(0xffffffffu, s, 1);
            s += __shfl_xor_sync(0xffffffffu, s, 2);
            if (q == 0) g_y2[k] = s;
        }
        float v = (tid < KK) ? lp[tid] : -1e30f;
        if (tid < KK) {
            float m = v;
            #pragma unroll
            for (int o = 16; o; o >>= 1) m = fmaxf(m, __shfl_xor_sync(0xffffffffu, m, o));
            if ((tid & 31) == 0) sm[tid >> 5] = m;
        }
        __syncthreads();
        if (tid < KK) {
            float M = fmaxf(sm[0], sm[1]);
            float e = __expf(v - M);
            float s = e;
            #pragma unroll
            for (int o = 16; o; o >>= 1) s += __shfl_xor_sync(0xffffffffu, s, o);
            if ((tid & 31) == 0) se[tid >> 5] = s;
        }
        __syncthreads();
        if (tid < KK) {
            float M = fmaxf(sm[0], sm[1]);
            float lb2 = (v - M) * 1.4426950408889634f - lg2a(se[0] + se[1]);
            g_lb2[tid] = lb2;
            g_bk[tid]  = ex2a(lb2);
        }
    }
}

// ---------------------------------------------------------------------------
__global__ __launch_bounds__(64, 10)
void node_kernel(const float* __restrict__ x,
                 const int*   __restrict__ bidx,
                 int n_nodes)
{
    int node = blockIdx.x;
    if (node >= n_nodes) return;
    const int t  = threadIdx.x;           // 0..63, owns column k=t
    const int w  = t >> 5;                // warp id
    const int l  = t & 31;                // lane
    const int fs = l & 15;                // f-direction row (warp-redundant)
    const int kh = l >> 4;                // f-direction k-half within warp

    __shared__ __align__(16) float uni[2048];
    float* const xsh  = uni;
    float* const Msh  = uni;                       // 16 x MST (overlays xsh)
    float* const Vb0  = uni + SS*MST;              // [64]
    float* const Vb1  = uni + SS*MST + KK;         // [64]
    __shared__ float x2sh[SS];
    __shared__ float redm[SS];
    __shared__ __align__(16) float f2[2][SS];      // warp-private u
    __shared__ float red2[2];

    // ---------------- stage x ----------------
    {
        const float4* xg4 = (const float4*)(x + (size_t)node * (SS*DD));
        float4* xs4 = (float4*)xsh;
        #pragma unroll
        for (int j = 0; j < 8; j++) xs4[t + 64*j] = xg4[t + 64*j];
    }
    __syncthreads();

    // ---------------- GEMM via FFMA2: dot[s] = <x_s, y_t> ----------------
    ull acc2[SS];
    #pragma unroll
    for (int s = 0; s < SS; s++) acc2[s] = 0ull;

    #pragma unroll 2
    for (int d4 = 0; d4 < 32; d4++) {
        const ulonglong2 yp = ((const ulonglong2*)g_ctf4)[d4*KK + t];
        #pragma unroll
        for (int s = 0; s < SS; s++) {
            ulonglong2 xp = *(const ulonglong2*)(xsh + s*DD + d4*4);
            ffma2(acc2[s], xp.x, yp.x);
            ffma2(acc2[s], xp.y, yp.y);
        }
    }
    float dot[SS];
    #pragma unroll
    for (int s = 0; s < SS; s++) dot[s] = unpack_add(acc2[s]);

    // ---------------- ||x_s||^2 : (s = t&15, d-quarter = t>>4) ----------------
    {
        const int xq = t >> 4;
        ull p2 = 0ull;
        #pragma unroll
        for (int i = 0; i < 8; i++) {
            ulonglong2 xp = *(const ulonglong2*)(xsh + fs*DD + xq*32 + i*4);
            ffma2(p2, xp.x, xp.x);
            ffma2(p2, xp.y, xp.y);
        }
        float x2p = unpack_add(p2);
        x2p += __shfl_xor_sync(0xffffffffu, x2p, 16);
        if (t >= 32 && t < 48) redm[fs] = x2p;
        __syncthreads();
        if (t < 16) x2sh[fs] = x2p + redm[fs];
        __syncthreads();
    }

    // ---------------- P = -C*log2e/eps ; Msh = P + log2 b ; sweep-1 g ----------
    const float y2k  = g_y2[t];
    const float lb2k = g_lb2[t];
    float P[SS];
    #pragma unroll
    for (int s = 0; s < SS; s++) {
        float Cv = fmaxf(x2sh[s] + y2k - 2.0f*dot[s], 0.0f);
        P[s] = -Cv * L2E_EPS;
        Msh[s*MST + t] = P[s] + lb2k;
    }
    float G1;
    {
        float m0 = fmaxf(P[0], P[1]), m1 = fmaxf(P[2], P[3]);
        float m2 = fmaxf(P[4], P[5]), m3 = fmaxf(P[6], P[7]);
        #pragma unroll
        for (int s = 8; s < SS; s += 4) {
            m0 = fmaxf(m0, P[s]);   m1 = fmaxf(m1, P[s+1]);
            m2 = fmaxf(m2, P[s+2]); m3 = fmaxf(m3, P[s+3]);
        }
        float m = fmaxf(fmaxf(m0, m1), fmaxf(m2, m3));
        float e = 0.0f;
        #pragma unroll
        for (int s = 0; s < SS; s++) e += ex2a(P[s] - m);
        G1 = -(m + lg2a(e));
        Vb0[t] = G1;
    }
    __syncthreads();

    // ---------------- sweep-1 f (log domain, warp-redundant) ----------------
    float Fcur;
    {
        const float4* Mr = (const float4*)(Msh + fs*MST + kh*32);
        const float4* Vr = (const float4*)(Vb0 + kh*32);
        float av[32];
        float mf = -1e30f;
        #pragma unroll
        for (int j = 0; j < 8; j++) {
            float4 a = Mr[j], b = Vr[j];
            av[4*j+0] = a.x + b.x; av[4*j+1] = a.y + b.y;
            av[4*j+2] = a.z + b.z; av[4*j+3] = a.w + b.w;
        }
        #pragma unroll
        for (int i = 0; i < 32; i++) mf = fmaxf(mf, av[i]);
        float ef = 0.0f;
        #pragma unroll
        for (int i = 0; i < 32; i++) ef += ex2a(av[i] - mf);
        float mo = __shfl_xor_sync(0xffffffffu, mf, 16);
        float eo = __shfl_xor_sync(0xffffffffu, ef, 16);
        float M2 = fmaxf(mf, mo);
        ef = ef*ex2a(mf - M2) + eo*ex2a(mo - M2);
        Fcur = -(M2 + lg2a(ef));
    }
    __syncthreads();                      // all Msh(P) reads done before Wb overwrite

    // ---------------- absorb (F1,G1): W2 regs + Wb into Msh ----------------
    ull W2[8];
    #pragma unroll
    for (int j = 0; j < 8; j++) {
        float Fa = __shfl_sync(0xffffffffu, Fcur, 2*j);
        float Fb = __shfl_sync(0xffffffffu, Fcur, 2*j+1);
        W2[j] = pk2(ex2a(Fa + G1 + P[2*j]), ex2a(Fb + G1 + P[2*j+1]));
    }
    if (w == 0) {
        float4* Mw = (float4*)(Msh + fs*MST + kh*32);
        const float4* Vr = (const float4*)(Vb0 + kh*32);
        #pragma unroll
        for (int j = 0; j < 8; j++) {
            float4 a = Mw[j], b = Vr[j];
            Mw[j] = make_float4(ex2a(Fcur + a.x + b.x), ex2a(Fcur + a.y + b.y),
                                ex2a(Fcur + a.z + b.z), ex2a(Fcur + a.w + b.w));
        }
    }
    if (l < 16) f2[w][l] = 1.0f;
    __syncwarp();

    // ---------------- 20 linear sweeps ----------------
    float vcur = 1.0f;
    const ull* const u2 = (const ull*)f2[w];
    const ulonglong2* const Wp = (const ulonglong2*)(Msh + fs*MST + kh*32);

    #pragma unroll 1
    for (int it = 1; it <= 20; it++) {
        float* gw = (it & 1) ? Vb1 : Vb0;
        // g: V_t = rcp( sum_s u_s W_st )
        ull a0 = 0ull, a1 = 0ull;
        #pragma unroll
        for (int j = 0; j < 8; j += 2) { ffma2(a0, u2[j], W2[j]); ffma2(a1, u2[j+1], W2[j+1]); }
        float cs = unpack_add(a0) + unpack_add(a1);
        vcur = rcpa(fmaxf(cs, 1e-30f));
        gw[t] = vcur;
        __syncthreads();
        // f: u_fs = rcp( sum_k V_k Wb_{fs,k} ), warp-redundant over 32-wide halves
        const ulonglong2* Vp = (const ulonglong2*)(gw + kh*32);
        ull b0 = 0ull, b1 = 0ull, b2 = 0ull, b3 = 0ull;
        #pragma unroll
        for (int j = 0; j < 8; j += 2) {
            ulonglong2 v0 = Vp[j],   w0 = Wp[j];
            ulonglong2 v1 = Vp[j+1], w1 = Wp[j+1];
            ffma2(b0, v0.x, w0.x); ffma2(b1, v0.y, w0.y);
            ffma2(b2, v1.x, w1.x); ffma2(b3, v1.y, w1.y);
        }
        float rs = (unpack_add(b0) + unpack_add(b1)) + (unpack_add(b2) + unpack_add(b3));
        rs += __shfl_xor_sync(0xffffffffu, rs, 16);
        float ucur = rcpa(fmaxf(rs, 1e-30f));
        if (l < 16) f2[w][l] = ucur;
        __syncwarp();

        // re-absorb (the underflow ratchet): it in {1,2,3,4,8,12,16}
        bool ab = (it <= 4) || (it == 8) || (it == 12) || (it == 16);
        if (ab) {
            __syncthreads();              // all f-phase Wb reads complete
            ull vv = pk2(vcur, vcur);
            #pragma unroll
            for (int j = 0; j < 8; j++) W2[j] = fmul2(W2[j], fmul2(u2[j], vv));
            if (w == 0) {
                float uf = f2[0][fs];
                float4* Mw = (float4*)(Msh + fs*MST + kh*32);
                const float4* Vr = (const float4*)(gw + kh*32);
                #pragma unroll
                for (int j = 0; j < 8; j++) {
                    float4 a = Mw[j], v = Vr[j];
                    Mw[j] = make_float4(a.x*(uf*v.x), a.y*(uf*v.y),
                                        a.z*(uf*v.z), a.w*(uf*v.w));
                }
            }
            __syncwarp();                 // W2/Wb reads of u done before reset
            if (l < 16) f2[w][l] = 1.0f;
            __syncwarp();
            // warp1 sees rescaled Wb at its next f-phase (after next g BAR)
        }
    }

    // ---------------- histogram: h_k = b_k * V_k * sum_s u_s W_sk ----------------
    {
        ull a0 = 0ull, a1 = 0ull;
        #pragma unroll
        for (int j = 0; j < 8; j += 2) { ffma2(a0, u2[j], W2[j]); ffma2(a1, u2[j+1], W2[j+1]); }
        float cs2 = unpack_add(a0) + unpack_add(a1);
        float hk = g_bk[t] * vcur * cs2;

        float ws = hk;
        #pragma unroll
        for (int o = 16; o; o >>= 1) ws += __shfl_xor_sync(0xffffffffu, ws, o);
        if (l == 0) red2[w] = ws;
        __syncthreads();
        float inv = rcpa(fmaxf(red2[0] + red2[1], 1e-30f));

        int b = bidx[node];
        atomicAdd(&g_sums[b*KK + t], hk * inv);
        if (t == 0) atomicAdd(&g_counts[b], 1.0f);
    }
}

// ---------------------------------------------------------------------------
__global__ void final_kernel(float* __restrict__ out, int B)
{
    int b = blockIdx.x, k = threadIdx.x;
    if (b >= B) return;
    float c = g_counts[b];
    float v = (c > 0.0f) ? (g_sums[b*KK + k] / c) : g_bk[k];
    out[b*KK + k] = v;
}

// ---------------------------------------------------------------------------
extern "C" void kernel_launch(void* const* d_in, const int* in_sizes, int n_in,
                              void* d_out, int out_size)
{
    const float* x    = (const float*)d_in[0];   // [N,16,128] f32
    const int*   bi   = (const int*)  d_in[1];   // [N] int32
    const float* cb   = (const float*)d_in[2];   // [64,128] f32
    const float* lp   = (const float*)d_in[3];   // [64] f32
    int N = in_sizes[1];
    int B = out_size / KK;
    if (B > BMAX) B = BMAX;

    prep_kernel<<<64, 256>>>(cb, lp);
    node_kernel<<<N, 64>>>(x, bi, N);
    final_kernel<<<B, KK>>>((float*)d_out, B);
}

// round 10
// speedup vs baseline: 1.3505x; 1.3505x over previous
#include <cuda_runtime.h>
#include <cuda_bf16.h>
#include <cstdint>

// BarycentricPooling — stabilized-linear Sinkhorn, R4 skeleton + packed sweeps
// + early convergence exit.
//
// N=20000, S=16, D=128, K=64, B=256, eps=0.1, 21 sweeps (1 log + <=20 linear).
//
// Block = 64 threads, one node. Thread t owns column k=t (g-direction);
// f-direction splits K in quarters (fs=t&15 row, fq=t>>4 quarter) with
// shfl(16) + smem merge (R4's proven 3-BAR structure, 332us).
//
// R7 lesson: __launch_bounds__(64,10) caused GEMM register spills (+33%).
// No launch bounds here. R6 lesson: absorbs at 4/8/12/16 are mandatory
// (underflow ratchet); kept identical to R4 so numerics match (4.49e-4).
//
// New vs R4: sweep math packed in fma.rn.f32x2 (u/V contiguous in smem ->
// LDS.64 pairs; W/Wb pair-packed regs), and a parity-flagged early exit when
// residual scalings converge to 1 (remaining sweeps are numeric no-ops).

#define SS    16
#define KK    64
#define DD    128
#define BMAX  256
#define MST   65   // Msh row stride (scalar access only)
#define L2E_EPS 14.4269504088896340736f   // log2(e)/0.1
#define CTOL  1e-5f

typedef unsigned long long ull;

__device__ float4 g_ctf4[(DD/4)*KK];   // codebook transposed: [d4][k] float4
__device__ float  g_y2[KK];
__device__ float  g_lb2[KK];
__device__ float  g_bk[KK];
__device__ float  g_sums[BMAX*KK];
__device__ float  g_counts[BMAX];

__device__ __forceinline__ float ex2a(float x){ float y; asm("ex2.approx.ftz.f32 %0, %1;" : "=f"(y) : "f"(x)); return y; }
__device__ __forceinline__ float lg2a(float x){ float y; asm("lg2.approx.ftz.f32 %0, %1;" : "=f"(y) : "f"(x)); return y; }
__device__ __forceinline__ float rcpa(float x){ float y; asm("rcp.approx.ftz.f32 %0, %1;" : "=f"(y) : "f"(x)); return y; }
__device__ __forceinline__ void ffma2(ull& d, ull a, ull b){
    asm("fma.rn.f32x2 %0, %1, %2, %0;" : "+l"(d) : "l"(a), "l"(b));
}
__device__ __forceinline__ ull fmul2(ull a, ull b){
    ull r; asm("mul.rn.f32x2 %0, %1, %2;" : "=l"(r) : "l"(a), "l"(b)); return r;
}
__device__ __forceinline__ float unpack_add(ull v){
    float lo = __uint_as_float((unsigned)(v & 0xffffffffull));
    float hi = __uint_as_float((unsigned)(v >> 32));
    return lo + hi;
}
__device__ __forceinline__ ull pk2(float lo, float hi){
    ull r; asm("mov.b64 %0, {%1,%2};" : "=l"(r) : "f"(lo), "f"(hi)); return r;
}

// ---------------------------------------------------------------------------
__global__ void prep_kernel(const float* __restrict__ cb,
                            const float* __restrict__ lp)
{
    __shared__ float sm[2], se[2];
    int tid = threadIdx.x;
    int i = blockIdx.x * blockDim.x + tid;

    if (i < BMAX*KK) g_sums[i] = 0.0f;
    if (i < BMAX)    g_counts[i] = 0.0f;
    if (i < (DD/4)*KK) {
        int d4 = i / KK, k = i % KK;
        const float* r = cb + k*DD + 4*d4;
        g_ctf4[i] = make_float4(r[0], r[1], r[2], r[3]);
    }
    if (blockIdx.x == 0) {
        if (tid < KK*4) {
            int k = tid >> 2, q = tid & 3;
            const float4* r = (const float4*)(cb + k*DD + q*32);
            float s = 0.0f;
            #pragma unroll
            for (int j = 0; j < 8; j++) { float4 v = r[j]; s += v.x*v.x + v.y*v.y + v.z*v.z + v.w*v.w; }
            s += __shfl_xor_sync(0xffffffffu, s, 1);
            s += __shfl_xor_sync(0xffffffffu, s, 2);
            if (q == 0) g_y2[k] = s;
        }
        float v = (tid < KK) ? lp[tid] : -1e30f;
        if (tid < KK) {
            float m = v;
            #pragma unroll
            for (int o = 16; o; o >>= 1) m = fmaxf(m, __shfl_xor_sync(0xffffffffu, m, o));
            if ((tid & 31) == 0) sm[tid >> 5] = m;
        }
        __syncthreads();
        if (tid < KK) {
            float M = fmaxf(sm[0], sm[1]);
            float e = __expf(v - M);
            float s = e;
            #pragma unroll
            for (int o = 16; o; o >>= 1) s += __shfl_xor_sync(0xffffffffu, s, o);
            if ((tid & 31) == 0) se[tid >> 5] = s;
        }
        __syncthreads();
        if (tid < KK) {
            float M = fmaxf(sm[0], sm[1]);
            float lb2 = (v - M) * 1.4426950408889634f - lg2a(se[0] + se[1]);
            g_lb2[tid] = lb2;
            g_bk[tid]  = ex2a(lb2);
        }
    }
}

// ---------------------------------------------------------------------------
__global__ void node_kernel(const float* __restrict__ x,
                            const int*   __restrict__ bidx,
                            int n_nodes)
{
    int node = blockIdx.x;
    if (node >= n_nodes) return;
    const int t  = threadIdx.x;           // 0..63, owns column k=t
    const int fs = t & 15;                // f-direction row
    const int fq = t >> 4;                // f-direction k-quarter

    // xsh (2048 f) overlaid by Msh (16x65) + g2s (64) after GEMM
    __shared__ __align__(16) float uni[2048];
    float* const xsh = uni;
    float* const Msh = uni;                         // 16 x MST (scalar access)
    float* const g2s = uni + SS*MST;                // [64], 16B-aligned (1040*4)
    __shared__ float x2sh[SS];
    __shared__ float redm[SS];
    __shared__ __align__(16) float f2[SS];          // F1 then residual u
    __shared__ float red2[2];
    __shared__ int   conv[2];

    // ---------------- stage x ----------------
    {
        const float4* xg4 = (const float4*)(x + (size_t)node * (SS*DD));
        float4* xs4 = (float4*)xsh;
        #pragma unroll
        for (int j = 0; j < 8; j++) xs4[t + 64*j] = xg4[t + 64*j];
    }
    __syncthreads();

    // ---------------- GEMM via FFMA2: dot[s] = <x_s, y_t> ----------------
    ull acc2[SS];
    #pragma unroll
    for (int s = 0; s < SS; s++) acc2[s] = 0ull;

    #pragma unroll 2
    for (int d4 = 0; d4 < 32; d4++) {
        const ulonglong2 yp = ((const ulonglong2*)g_ctf4)[d4*KK + t];
        #pragma unroll
        for (int s = 0; s < SS; s++) {
            ulonglong2 xp = *(const ulonglong2*)(xsh + s*DD + d4*4);
            ffma2(acc2[s], xp.x, yp.x);
            ffma2(acc2[s], xp.y, yp.y);
        }
    }
    float dot[SS];
    #pragma unroll
    for (int s = 0; s < SS; s++) dot[s] = unpack_add(acc2[s]);

    // ---------------- ||x_s||^2 : (s = t&15, d-quarter = t>>4) ----------------
    {
        ull p2 = 0ull;
        #pragma unroll
        for (int i = 0; i < 8; i++) {
            ulonglong2 xp = *(const ulonglong2*)(xsh + fs*DD + fq*32 + i*4);
            ffma2(p2, xp.x, xp.x);
            ffma2(p2, xp.y, xp.y);
        }
        float x2p = unpack_add(p2);
        x2p += __shfl_xor_sync(0xffffffffu, x2p, 16);
        if (t >= 32 && t < 48) redm[fs] = x2p;
        __syncthreads();                  // also: all xsh reads complete
        if (t < 16) x2sh[fs] = x2p + redm[fs];
        __syncthreads();
    }

    // ---------------- P = -C*log2e/eps ; Msh = P + log2 b ; sweep-1 g ----------
    const float y2k  = g_y2[t];
    const float lb2k = g_lb2[t];
    float P[SS];
    #pragma unroll
    for (int s = 0; s < SS; s++) {
        float Cv = fmaxf(x2sh[s] + y2k - 2.0f*dot[s], 0.0f);
        P[s] = -Cv * L2E_EPS;
        Msh[s*MST + t] = P[s] + lb2k;     // overlays dead xsh
    }
    float G1;
    {
        float m = P[0];
        #pragma unroll
        for (int s = 1; s < SS; s++) m = fmaxf(m, P[s]);
        float e = 0.0f;
        #pragma unroll
        for (int s = 0; s < SS; s++) e += ex2a(P[s] - m);
        G1 = -(m + lg2a(e));
        g2s[t] = G1;
    }
    __syncthreads();

    // ---------------- sweep-1 f (log domain, quarter split) ----------------
    {
        float af[16];
        float mf = -1e30f;
        #pragma unroll
        for (int j = 0; j < 16; j++) {
            int k = fq*16 + j;
            af[j] = g2s[k] + Msh[fs*MST + k];
            mf = fmaxf(mf, af[j]);
        }
        float ef = 0.0f;
        #pragma unroll
        for (int j = 0; j < 16; j++) ef += ex2a(af[j] - mf);
        float mo = __shfl_xor_sync(0xffffffffu, mf, 16);
        float eo = __shfl_xor_sync(0xffffffffu, ef, 16);
        float M2 = fmaxf(mf, mo);
        ef = ef*ex2a(mf - M2) + eo*ex2a(mo - M2);
        if (t >= 32 && t < 48) { redm[fs] = M2; red2[0] = 0.0f; x2sh[fs] = ef; }
        __syncthreads();
        if (t < 16) {
            float M3 = fmaxf(M2, redm[fs]);
            float E  = ef*ex2a(M2 - M3) + x2sh[fs]*ex2a(redm[fs] - M3);
            f2[fs] = -(M3 + lg2a(E));     // F1
        }
        __syncthreads();
    }

    // ---------------- absorb (F1,G1): W2 + Wbq2 packed registers ----------------
    ull W2[8];                            // W[s-pair] for own column t
    #pragma unroll
    for (int j = 0; j < 8; j++)
        W2[j] = pk2(ex2a(f2[2*j] + G1 + P[2*j]), ex2a(f2[2*j+1] + G1 + P[2*j+1]));

    ull Wbq2[8];                          // Wb[fs][k-pair], quarter fq
    {
        float F1fs = f2[fs];
        #pragma unroll
        for (int j = 0; j < 8; j++) {
            int k = fq*16 + 2*j;
            float wa = ex2a(F1fs + g2s[k]   + Msh[fs*MST + k]);
            float wb = ex2a(F1fs + g2s[k+1] + Msh[fs*MST + k+1]);
            Wbq2[j] = pk2(wa, wb);
        }
    }
    __syncthreads();                      // g2s(G1)/f2(F1) reads done
    if (t < 16) f2[t] = 1.0f;
    if (t == 0) { conv[0] = 1; conv[1] = 1; }
    __syncthreads();

    // ---------------- linear sweeps with early exit ----------------
    float vcur = 1.0f;
    const ull* const u2 = (const ull*)f2;

    #pragma unroll 1
    for (int it = 1; it <= 20; it++) {
        const int par = it & 1;
        // g: V_t = rcp( sum_s u_s W_st )
        ull a0 = 0ull, a1 = 0ull;
        #pragma unroll
        for (int j = 0; j < 8; j += 2) { ffma2(a0, u2[j], W2[j]); ffma2(a1, u2[j+1], W2[j+1]); }
        float cs = unpack_add(a0) + unpack_add(a1);
        vcur = rcpa(fmaxf(cs, 1e-30f));
        if (fabsf(vcur - 1.0f) > CTOL) conv[par] = 0;   // benign race (all write 0)
        g2s[t] = vcur;
        __syncthreads();
        if (t == 0) conv[par ^ 1] = 1;    // prep next iter's flag (slot idle now)
        // f: u_fs = rcp( sum_k V_k Wb_{fs,k} ), quarter split
        const ull* Vp = (const ull*)(g2s + fq*16);
        ull b0 = 0ull, b1 = 0ull;
        #pragma unroll
        for (int j = 0; j < 8; j += 2) { ffma2(b0, Vp[j], Wbq2[j]); ffma2(b1, Vp[j+1], Wbq2[j+1]); }
        float rs = unpack_add(b0) + unpack_add(b1);
        rs += __shfl_xor_sync(0xffffffffu, rs, 16);
        if (t >= 32 && t < 48) redm[fs] = rs;
        __syncthreads();
        if (t < 16) {
            float ucur = rcpa(fmaxf(rs + redm[fs], 1e-30f));
            if (fabsf(ucur - 1.0f) > CTOL) conv[par] = 0;
            f2[fs] = ucur;
        }
        __syncthreads();
        if (conv[par]) break;             // converged: rest are numeric no-ops

        // re-absorb every 4 (underflow ratchet; R4-validated schedule)
        if ((it & 3) == 0 && it != 20) {
            ull vv = pk2(vcur, vcur);
            #pragma unroll
            for (int j = 0; j < 8; j++) W2[j] = fmul2(W2[j], fmul2(u2[j], vv));
            float uf = f2[fs];
            ull  uu = pk2(uf, uf);
            const ull* Vq = (const ull*)(g2s + fq*16);
            #pragma unroll
            for (int j = 0; j < 8; j++) Wbq2[j] = fmul2(Wbq2[j], fmul2(uu, Vq[j]));
            __syncthreads();              // all absorb reads of f2/g2s done
            if (t < 16) f2[t] = 1.0f;
            __syncthreads();
        }
    }

    // ---------------- histogram: h_k = b_k * V_k * sum_s u_s W_sk ----------------
    {
        ull a0 = 0ull, a1 = 0ull;
        #pragma unroll
        for (int j = 0; j < 8; j += 2) { ffma2(a0, u2[j], W2[j]); ffma2(a1, u2[j+1], W2[j+1]); }
        float cs2 = unpack_add(a0) + unpack_add(a1);
        float hk = g_bk[t] * vcur * cs2;

        float ws = hk;
        #pragma unroll
        for (int o = 16; o; o >>= 1) ws += __shfl_xor_sync(0xffffffffu, ws, o);
        if ((t & 31) == 0) red2[t >> 5] = ws;
        __syncthreads();
        float inv = rcpa(fmaxf(red2[0] + red2[1], 1e-30f));

        int b = bidx[node];
        atomicAdd(&g_sums[b*KK + t], hk * inv);
        if (t == 0) atomicAdd(&g_counts[b], 1.0f);
    }
}

// ---------------------------------------------------------------------------
__global__ void final_kernel(float* __restrict__ out, int B)
{
    int b = blockIdx.x, k = threadIdx.x;
    if (b >= B) return;
    float c = g_counts[b];
    float v = (c > 0.0f) ? (g_sums[b*KK + k] / c) : g_bk[k];
    out[b*KK + k] = v;
}

// ---------------------------------------------------------------------------
extern "C" void kernel_launch(void* const* d_in, const int* in_sizes, int n_in,
                              void* d_out, int out_size)
{
    const float* x    = (const float*)d_in[0];   // [N,16,128] f32
    const int*   bi   = (const int*)  d_in[1];   // [N] int32
    const float* cb   = (const float*)d_in[2];   // [64,128] f32
    const float* lp   = (const float*)d_in[3];   // [64] f32
    int N = in_sizes[1];
    int B = out_size / KK;
    if (B > BMAX) B = BMAX;

    prep_kernel<<<64, 256>>>(cb, lp);
    node_kernel<<<N, 64>>>(x, bi, N);
    final_kernel<<<B, KK>>>((float*)d_out, B);
}